// round 1
// baseline (speedup 1.0000x reference)
#include <cuda_runtime.h>
#include <math.h>

#define NB 256
#define NS 32
#define NL 32
#define ND 256
#define NE 64

// -------- scratch (static device globals; no runtime allocation) --------
__device__ float g_enc[NB*NS*ND];   // 8 MB  enc[b,s,d]
__device__ float g_eW [NB*NS*ND];   // 8 MB  (enc @ W)[b,s,d]
__device__ float g_kV [NB*NE*ND];   // 16 MB (keys @ V)[b,j,d]
__device__ float g_ht [NB*NE*ND];   // 16 MB per-step candidate h_t
__device__ int   g_act[NB*NS];

// ---------------- encode: enc[b,s,d] = sum_l emb[tok[b,s,l],d]*mask ----------------
__global__ void encode_kernel(const int* __restrict__ tok,
                              const float* __restrict__ mask,
                              const float* __restrict__ emb) {
    int bs = blockIdx.x;          // b*NS + s
    int d  = threadIdx.x;         // 0..255
    const int*   t = tok  + (size_t)bs*NL;
    const float* m = mask + (size_t)bs*NL;
    float acc = 0.f, ms = 0.f;
    #pragma unroll
    for (int l = 0; l < NL; ++l) {
        float mv = __ldg(m + l);
        int   tv = __ldg(t + l);
        acc += mv * __ldg(emb + (size_t)tv*ND + d);
        ms  += mv;
    }
    g_enc[(size_t)bs*ND + d] = acc;
    if (d == 0) g_act[bs] = (ms > 0.f) ? 1 : 0;
}

// ---------------- GEMM: C[M,256] = A[M,256] @ Bm[256,256] ----------------
// MODE 0: C = A@B
// MODE 1: C = relu(A@B + add1[row,col] + add2[(row/NE)*NS + s, col])
// BM=128, BN=128, BK=8, 256 threads, 8x8 per thread.
template<int MODE>
__global__ __launch_bounds__(256, 2)
void gemm_kernel(const float* __restrict__ A, const float* __restrict__ Bm,
                 float* __restrict__ C,
                 const float* __restrict__ add1,
                 const float* __restrict__ add2, int s) {
    const int BK = 8;
    __shared__ float As[BK][128];
    __shared__ float Bs[BK][128];

    const int tid  = threadIdx.x;
    const int trow = tid >> 4;          // 0..15 (M dir)
    const int tcol = tid & 15;          // 0..15 (N dir)
    const int rowBase = blockIdx.y * 128;
    const int colBase = blockIdx.x * 128;

    // A tile load: thread t -> row t/2, k-offset (t&1)*4, one float4
    const int aRow = tid >> 1;
    const int aK4  = (tid & 1) * 4;
    // B tile load: thread t -> k-row t/32, col 4*(t%32), one float4
    const int bK   = tid >> 5;
    const int bCol = (tid & 31) * 4;

    float acc[8][8];
    #pragma unroll
    for (int i = 0; i < 8; i++)
        #pragma unroll
        for (int j = 0; j < 8; j++) acc[i][j] = 0.f;

    const float* Ag = A  + (size_t)(rowBase + aRow)*ND + aK4;
    const float* Bg = Bm + (size_t)bK*ND + colBase + bCol;

    for (int k0 = 0; k0 < ND; k0 += BK) {
        float4 av = *(const float4*)(Ag + k0);
        As[aK4+0][aRow] = av.x;
        As[aK4+1][aRow] = av.y;
        As[aK4+2][aRow] = av.z;
        As[aK4+3][aRow] = av.w;
        *(float4*)(&Bs[bK][bCol]) = *(const float4*)(Bg + (size_t)k0*ND);
        __syncthreads();
        #pragma unroll
        for (int k = 0; k < BK; k++) {
            float rm[8], rn[8];
            *(float4*)(rm)     = *(const float4*)(&As[k][trow*8]);
            *(float4*)(rm + 4) = *(const float4*)(&As[k][trow*8 + 4]);
            *(float4*)(rn)     = *(const float4*)(&Bs[k][tcol*8]);
            *(float4*)(rn + 4) = *(const float4*)(&Bs[k][tcol*8 + 4]);
            #pragma unroll
            for (int i = 0; i < 8; i++)
                #pragma unroll
                for (int j = 0; j < 8; j++)
                    acc[i][j] = fmaf(rm[i], rn[j], acc[i][j]);
        }
        __syncthreads();
    }

    #pragma unroll
    for (int i = 0; i < 8; i++) {
        int row = rowBase + trow*8 + i;
        int col = colBase + tcol*8;
        size_t off = (size_t)row*ND + col;
        if (MODE == 0) {
            *(float4*)(C + off)     = make_float4(acc[i][0], acc[i][1], acc[i][2], acc[i][3]);
            *(float4*)(C + off + 4) = make_float4(acc[i][4], acc[i][5], acc[i][6], acc[i][7]);
        } else {
            int b = row / NE;
            size_t eoff = ((size_t)b*NS + s)*ND + col;
            float4 a10 = *(const float4*)(add1 + off);
            float4 a11 = *(const float4*)(add1 + off + 4);
            float4 a20 = *(const float4*)(add2 + eoff);
            float4 a21 = *(const float4*)(add2 + eoff + 4);
            float o0 = fmaxf(acc[i][0] + a10.x + a20.x, 0.f);
            float o1 = fmaxf(acc[i][1] + a10.y + a20.y, 0.f);
            float o2 = fmaxf(acc[i][2] + a10.z + a20.z, 0.f);
            float o3 = fmaxf(acc[i][3] + a10.w + a20.w, 0.f);
            float o4 = fmaxf(acc[i][4] + a11.x + a21.x, 0.f);
            float o5 = fmaxf(acc[i][5] + a11.y + a21.y, 0.f);
            float o6 = fmaxf(acc[i][6] + a11.z + a21.z, 0.f);
            float o7 = fmaxf(acc[i][7] + a11.w + a21.w, 0.f);
            *(float4*)(C + off)     = make_float4(o0, o1, o2, o3);
            *(float4*)(C + off + 4) = make_float4(o4, o5, o6, o7);
        }
    }
}

// ---------------- per-step update: gate, add, renormalize ----------------
// one block per (b,j) row, 256 threads = D
__global__ void update_kernel(float* __restrict__ h,
                              const float* __restrict__ keys,
                              int s) {
    int row = blockIdx.x;           // b*NE + j
    int b   = row >> 6;             // NE = 64
    if (!g_act[b*NS + s]) return;   // uniform per block -> safe with barriers

    int d = threadIdx.x;
    size_t off = (size_t)row*ND + d;
    float hv = h[off];
    float kv = keys[off];
    float ev = g_enc[((size_t)b*NS + s)*ND + d];

    __shared__ float sm1[8];
    __shared__ float sm2[8];
    int lane = d & 31, w = d >> 5;

    // gate dot: sum_d ev*(hv+kv)
    float p = ev * (hv + kv);
    #pragma unroll
    for (int o = 16; o > 0; o >>= 1) p += __shfl_xor_sync(0xffffffffu, p, o);
    if (lane == 0) sm1[w] = p;
    __syncthreads();
    float dot = sm1[0]+sm1[1]+sm1[2]+sm1[3]+sm1[4]+sm1[5]+sm1[6]+sm1[7];
    float g = 1.f / (1.f + expf(-dot));

    float hn = hv + g * g_ht[off];

    // squared norm
    float q = hn * hn;
    #pragma unroll
    for (int o = 16; o > 0; o >>= 1) q += __shfl_xor_sync(0xffffffffu, q, o);
    if (lane == 0) sm2[w] = q;
    __syncthreads();
    float sq = sm2[0]+sm2[1]+sm2[2]+sm2[3]+sm2[4]+sm2[5]+sm2[6]+sm2[7];
    float r = rsqrtf(fmaxf(sq, 1e-12f));

    h[off] = hn * r;
}

extern "C" void kernel_launch(void* const* d_in, const int* in_sizes, int n_in,
                              void* d_out, int out_size) {
    const int*   tok  = (const int*)  d_in[0];  // first_prgrph (B,S,L) int32
    const float* mask = (const float*)d_in[1];  // p1_mask (B,S,L)
    const float* keys = (const float*)d_in[2];  // entity_keys (B,E,D)
    const float* emb  = (const float*)d_in[3];  // embedding_matrix (VOCAB,D)
    const float* U    = (const float*)d_in[4];
    const float* V    = (const float*)d_in[5];
    const float* W    = (const float*)d_in[6];
    float* h = (float*)d_out;                   // (B,E,D) fp32, used as state

    float *enc, *eW, *kV, *ht;
    cudaGetSymbolAddress((void**)&enc, g_enc);
    cudaGetSymbolAddress((void**)&eW,  g_eW);
    cudaGetSymbolAddress((void**)&kV,  g_kV);
    cudaGetSymbolAddress((void**)&ht,  g_ht);

    // 1) encode: enc + active flags
    encode_kernel<<<NB*NS, ND>>>(tok, mask, emb);

    // 2) loop-invariant GEMMs: kV = keys@V  (M=16384), eW = enc@W (M=8192)
    gemm_kernel<0><<<dim3(2, (NB*NE)/128), 256>>>(keys, V, kV, nullptr, nullptr, 0);
    gemm_kernel<0><<<dim3(2, (NB*NS)/128), 256>>>(enc,  W, eW, nullptr, nullptr, 0);

    // 3) h = 0
    cudaMemsetAsync(h, 0, (size_t)NB*NE*ND*sizeof(float), 0);

    // 4) recurrence over S steps
    for (int s = 0; s < NS; ++s) {
        // ht = relu(h@U + kV + eW[:,s,:] broadcast)
        gemm_kernel<1><<<dim3(2, (NB*NE)/128), 256>>>(h, U, ht, kV, eW, s);
        // h = normalize(h + sigmoid(<enc_s, h+keys>) * ht)
        update_kernel<<<NB*NE, ND>>>(h, keys, s);
    }
}

// round 3
// speedup vs baseline: 1.7978x; 1.7978x over previous
#include <cuda_runtime.h>
#include <cuda_bf16.h>
#include <cstdint>
#include <math.h>

#define NB 256
#define NS 32
#define NL 32
#define ND 256
#define NE 64
#define KBIG 768          // concatenated K: [hi | hi | lo] x [Uhi ; Ulo ; Uhi]

// ===================== scratch (device globals; no runtime alloc) =====================
__device__ float g_enc[NB*NS*ND];            // enc[b,s,d]
__device__ float g_eW [NB*NS*ND];            // enc @ W
__device__ float g_kV [NB*NE*ND];            // keys @ V
__device__ int   g_act[NB*NS];
__device__ __nv_bfloat16 g_Bt[ND*KBIG];      // Bt[n][k]: [Uhi^T | Ulo^T | Uhi^T]
__device__ __nv_bfloat16 g_hA_hi[NB*NE*ND];  // h split hi (row,k)
__device__ __nv_bfloat16 g_hA_lo[NB*NE*ND];  // h split lo

// ===================== PTX wrappers (sm_80-level features only) =====================
__device__ __forceinline__ uint32_t smem_u32(const void* p) {
    uint32_t a;
    asm("{ .reg .u64 t; cvta.to.shared.u64 t, %1; cvt.u32.u64 %0, t; }" : "=r"(a) : "l"(p));
    return a;
}
__device__ __forceinline__ void cpa16(uint32_t dst, const void* src) {
    asm volatile("cp.async.cg.shared.global [%0], [%1], 16;" :: "r"(dst), "l"(src));
}
#define CP_COMMIT() asm volatile("cp.async.commit_group;" ::: "memory")
#define CP_WAIT1()  asm volatile("cp.async.wait_group 1;"  ::: "memory")

__device__ __forceinline__ void ldsm_x4(uint32_t* r, uint32_t addr) {
    asm volatile("ldmatrix.sync.aligned.m8n8.x4.shared.b16 {%0,%1,%2,%3}, [%4];"
        : "=r"(r[0]), "=r"(r[1]), "=r"(r[2]), "=r"(r[3]) : "r"(addr));
}
__device__ __forceinline__ void ldsm_x2(uint32_t* r, uint32_t addr) {
    asm volatile("ldmatrix.sync.aligned.m8n8.x2.shared.b16 {%0,%1}, [%2];"
        : "=r"(r[0]), "=r"(r[1]) : "r"(addr));
}
__device__ __forceinline__ void mma_bf16(float* d, const uint32_t* a, const uint32_t* b) {
    asm volatile("mma.sync.aligned.m16n8k16.row.col.f32.bf16.bf16.f32 "
        "{%0,%1,%2,%3}, {%4,%5,%6,%7}, {%8,%9}, {%0,%1,%2,%3};"
        : "+f"(d[0]), "+f"(d[1]), "+f"(d[2]), "+f"(d[3])
        : "r"(a[0]), "r"(a[1]), "r"(a[2]), "r"(a[3]), "r"(b[0]), "r"(b[1]));
}

// ===================== SMEM layout for step kernel =====================
// rows padded to 72 bf16 = 144B  -> conflict-free ldmatrix (144 mod 128 = 16)
#define SM_GS   0                      // 128 floats: gate
#define SM_RSQ  512                    // 128 floats: row sumsq / rsqrt
#define SM_ACTS 1024                   // 128 ints
#define SM_TILE 2048
#define A_TILE_B (128*144)             // 18432
#define B_TILE_B (256*144)             // 36864
#define SM_A0 (SM_TILE)
#define SM_A1 (SM_A0 + A_TILE_B)
#define SM_B0 (SM_A1 + A_TILE_B)
#define SM_B1 (SM_B0 + B_TILE_B)
#define SM_BUF SM_TILE                 // epilogue fp32 buf 128x257 (reuses tiles)
#define SMEM_BYTES (SM_TILE + 128*257*4)   // 133,632 B  (> tile usage 112,640)

// ===================== encode =====================
__global__ void encode_kernel(const int* __restrict__ tok, const float* __restrict__ mask,
                              const float* __restrict__ emb) {
    int bs = blockIdx.x, d = threadIdx.x;
    const int*   t = tok  + (size_t)bs*NL;
    const float* m = mask + (size_t)bs*NL;
    float acc = 0.f, ms = 0.f;
    #pragma unroll
    for (int l = 0; l < NL; ++l) {
        float mv = __ldg(m + l);
        int   tv = __ldg(t + l);
        acc += mv * __ldg(emb + (size_t)tv*ND + d);
        ms  += mv;
    }
    g_enc[(size_t)bs*ND + d] = acc;
    if (d == 0) g_act[bs] = (ms > 0.f) ? 1 : 0;
}

// ===================== prep: Bt[n][k] = [Uhi^T | Ulo^T | Uhi^T] =====================
__global__ void prep_bt_kernel(const float* __restrict__ U) {
    int n = blockIdx.x, k = threadIdx.x;
    float v = U[(size_t)k*ND + n];
    __nv_bfloat16 hi = __float2bfloat16(v);
    __nv_bfloat16 lo = __float2bfloat16(v - __bfloat162float(hi));
    g_Bt[(size_t)n*KBIG + k]        = hi;
    g_Bt[(size_t)n*KBIG + 256 + k]  = lo;
    g_Bt[(size_t)n*KBIG + 512 + k]  = hi;
}

// ===================== SIMT fp32 GEMM (loop-invariant products, runs once) ===========
__global__ __launch_bounds__(256, 2)
void gemm0_kernel(const float* __restrict__ A, const float* __restrict__ Bm, float* __restrict__ C) {
    const int BK = 8;
    __shared__ float As[BK][128];
    __shared__ float Bs[BK][128];
    const int tid = threadIdx.x;
    const int trow = tid >> 4, tcol = tid & 15;
    const int rowBase = blockIdx.y * 128, colBase = blockIdx.x * 128;
    const int aRow = tid >> 1, aK4 = (tid & 1) * 4;
    const int bK = tid >> 5, bCol = (tid & 31) * 4;
    float acc[8][8];
    #pragma unroll
    for (int i = 0; i < 8; i++)
        #pragma unroll
        for (int j = 0; j < 8; j++) acc[i][j] = 0.f;
    const float* Ag = A  + (size_t)(rowBase + aRow)*ND + aK4;
    const float* Bg = Bm + (size_t)bK*ND + colBase + bCol;
    for (int k0 = 0; k0 < ND; k0 += BK) {
        float4 av = *(const float4*)(Ag + k0);
        As[aK4+0][aRow] = av.x; As[aK4+1][aRow] = av.y;
        As[aK4+2][aRow] = av.z; As[aK4+3][aRow] = av.w;
        *(float4*)(&Bs[bK][bCol]) = *(const float4*)(Bg + (size_t)k0*ND);
        __syncthreads();
        #pragma unroll
        for (int k = 0; k < BK; k++) {
            float rm[8], rn[8];
            *(float4*)(rm)     = *(const float4*)(&As[k][trow*8]);
            *(float4*)(rm + 4) = *(const float4*)(&As[k][trow*8 + 4]);
            *(float4*)(rn)     = *(const float4*)(&Bs[k][tcol*8]);
            *(float4*)(rn + 4) = *(const float4*)(&Bs[k][tcol*8 + 4]);
            #pragma unroll
            for (int i = 0; i < 8; i++)
                #pragma unroll
                for (int j = 0; j < 8; j++)
                    acc[i][j] = fmaf(rm[i], rn[j], acc[i][j]);
        }
        __syncthreads();
    }
    #pragma unroll
    for (int i = 0; i < 8; i++) {
        size_t off = (size_t)(rowBase + trow*8 + i)*ND + colBase + tcol*8;
        *(float4*)(C + off)     = make_float4(acc[i][0], acc[i][1], acc[i][2], acc[i][3]);
        *(float4*)(C + off + 4) = make_float4(acc[i][4], acc[i][5], acc[i][6], acc[i][7]);
    }
}

// ===================== fused step: HMMA split-bf16 GEMM + gate + norm ================
__global__ void __launch_bounds__(512, 1)
step_kernel(const float* __restrict__ keys, float* __restrict__ h, int s) {
    extern __shared__ char smem[];
    const uint32_t sb = smem_u32(smem);
    const int tid    = threadIdx.x;
    const int lane   = tid & 31;
    const int wid    = tid >> 5;
    const int warp_m = wid >> 2;          // 0..3 -> 32 rows each
    const int warp_n = wid & 3;           // 0..3 -> 64 cols each
    const int rowBase = blockIdx.x * 128;

    float* gs    = (float*)(smem + SM_GS);
    float* rsq   = (float*)(smem + SM_RSQ);
    int*   acts  = (int*)  (smem + SM_ACTS);

    // ---------- phase 0: gate dot + init smem ----------
    {
        int r = tid >> 2, part = tid & 3;       // 4 threads per row
        int grow = rowBase + r;
        int b = grow >> 6;
        const float* encRow = g_enc + ((size_t)b*NS + s)*ND + part*64;
        const float* hRow   = h     + (size_t)grow*ND + part*64;
        const float* kRow   = keys  + (size_t)grow*ND + part*64;
        float d = 0.f;
        #pragma unroll
        for (int i = 0; i < 16; i++) {
            float4 e  = ((const float4*)encRow)[i];
            float4 hv = ((const float4*)hRow)[i];
            float4 kv = ((const float4*)kRow)[i];
            d += e.x*(hv.x+kv.x) + e.y*(hv.y+kv.y) + e.z*(hv.z+kv.z) + e.w*(hv.w+kv.w);
        }
        d += __shfl_xor_sync(0xffffffffu, d, 1);
        d += __shfl_xor_sync(0xffffffffu, d, 2);
        if (part == 0) {
            gs[r]   = 1.f / (1.f + expf(-d));
            rsq[r]  = 0.f;
            acts[r] = g_act[b*NS + s];
        }
    }
    __syncthreads();

    // ---------- mainloop: C[128,256] += Abig[128,768] @ Bt^T, 12 chunks of K=64 ------
    const __nv_bfloat16* hi = g_hA_hi + (size_t)rowBase*ND;
    const __nv_bfloat16* lo = g_hA_lo + (size_t)rowBase*ND;

    float acc[2][8][4];
    #pragma unroll
    for (int mt = 0; mt < 2; mt++)
        #pragma unroll
        for (int nt = 0; nt < 8; nt++)
            #pragma unroll
            for (int q = 0; q < 4; q++) acc[mt][nt][q] = 0.f;

    // per-thread ldmatrix address offsets (bytes)
    const int selA = lane >> 3;
    const uint32_t aoff = (uint32_t)(((selA & 1)*8 + (lane & 7))*144 + (selA >> 1)*16);
    const int l16 = lane & 15;
    const uint32_t boff = (uint32_t)((l16 & 7)*144 + (l16 >> 3)*16);

    auto load_chunk = [&](int c, int bufsel) {
        const __nv_bfloat16* asrc = ((c < 8) ? hi : lo) + (c & 3)*64;
        const __nv_bfloat16* bsrc = g_Bt + c*64;
        uint32_t adst = sb + (bufsel ? SM_A1 : SM_A0);
        uint32_t bdst = sb + (bufsel ? SM_B1 : SM_B0);
        #pragma unroll
        for (int i = 0; i < 2; i++) {
            int idx = tid + i*512, row = idx >> 3, seg = idx & 7;
            cpa16(adst + row*144 + seg*16, asrc + (size_t)row*ND + seg*8);
        }
        #pragma unroll
        for (int i = 0; i < 4; i++) {
            int idx = tid + i*512, n = idx >> 3, seg = idx & 7;
            cpa16(bdst + n*144 + seg*16, bsrc + (size_t)n*KBIG + seg*8);
        }
    };

    load_chunk(0, 0);
    CP_COMMIT();

    for (int c = 0; c < 12; ++c) {
        if (c + 1 < 12) load_chunk(c + 1, (c + 1) & 1);
        CP_COMMIT();
        CP_WAIT1();
        __syncthreads();

        const uint32_t abase = sb + ((c & 1) ? SM_A1 : SM_A0) + (warp_m*32)*144 + aoff;
        const uint32_t bbase = sb + ((c & 1) ? SM_B1 : SM_B0) + (warp_n*64)*144 + boff;

        #pragma unroll
        for (int k4 = 0; k4 < 4; ++k4) {
            const uint32_t kb = k4 * 32;     // k*2 bytes
            uint32_t a0[4], a1[4];
            ldsm_x4(a0, abase + kb);
            ldsm_x4(a1, abase + 16*144 + kb);
            #pragma unroll
            for (int nt = 0; nt < 8; ++nt) {
                uint32_t bfrag[2];
                ldsm_x2(bfrag, bbase + nt*8*144 + kb);
                mma_bf16(acc[0][nt], a0, bfrag);
                mma_bf16(acc[1][nt], a1, bfrag);
            }
        }
        __syncthreads();
    }

    // ---------- epilogue pass 1: relu-add, gated update, row sumsq ----------
    float* buf = (float*)(smem + SM_BUF);
    #pragma unroll
    for (int mt = 0; mt < 2; mt++) {
        int rA = warp_m*32 + mt*16 + (lane >> 2);
        int rB = rA + 8;
        int gA = rowBase + rA, gB = rowBase + rB;
        int bA = gA >> 6,      bB = gB >> 6;
        const float* kvA = g_kV + (size_t)gA*ND;
        const float* kvB = g_kV + (size_t)gB*ND;
        const float* ewA = g_eW + ((size_t)bA*NS + s)*ND;
        const float* ewB = g_eW + ((size_t)bB*NS + s)*ND;
        const float* hA  = h    + (size_t)gA*ND;
        const float* hB  = h    + (size_t)gB*ND;
        float gateA = gs[rA], gateB = gs[rB];
        float sA = 0.f, sB = 0.f;
        #pragma unroll
        for (int nt = 0; nt < 8; nt++) {
            int col = warp_n*64 + nt*8 + 2*(lane & 3);
            float2 kv, ew, ho;
            kv = *(const float2*)(kvA + col); ew = *(const float2*)(ewA + col); ho = *(const float2*)(hA + col);
            float v0 = fmaxf(acc[mt][nt][0] + kv.x + ew.x, 0.f);
            float v1 = fmaxf(acc[mt][nt][1] + kv.y + ew.y, 0.f);
            float h0 = ho.x + gateA*v0, h1 = ho.y + gateA*v1;
            buf[rA*257 + col] = h0; buf[rA*257 + col + 1] = h1;
            sA += h0*h0 + h1*h1;
            kv = *(const float2*)(kvB + col); ew = *(const float2*)(ewB + col); ho = *(const float2*)(hB + col);
            float w0 = fmaxf(acc[mt][nt][2] + kv.x + ew.x, 0.f);
            float w1 = fmaxf(acc[mt][nt][3] + kv.y + ew.y, 0.f);
            float h2 = ho.x + gateB*w0, h3 = ho.y + gateB*w1;
            buf[rB*257 + col] = h2; buf[rB*257 + col + 1] = h3;
            sB += h2*h2 + h3*h3;
        }
        sA += __shfl_xor_sync(0xffffffffu, sA, 1);
        sA += __shfl_xor_sync(0xffffffffu, sA, 2);
        sB += __shfl_xor_sync(0xffffffffu, sB, 1);
        sB += __shfl_xor_sync(0xffffffffu, sB, 2);
        if ((lane & 3) == 0) {
            atomicAdd(&rsq[rA], sA);
            atomicAdd(&rsq[rB], sB);
        }
    }
    __syncthreads();
    if (tid < 128) rsq[tid] = rsqrtf(fmaxf(rsq[tid], 1e-12f));
    __syncthreads();

    // ---------- epilogue pass 2: normalize + write h and bf16 hi/lo split ----------
    #pragma unroll
    for (int i = 0; i < 64; i++) {
        int idx = tid + i*512;
        int row = idx >> 8, col = idx & 255;
        if (acts[row]) {
            float v = buf[row*257 + col] * rsq[row];
            size_t go = (size_t)(rowBase + row)*ND + col;
            h[go] = v;
            __nv_bfloat16 vh = __float2bfloat16(v);
            g_hA_hi[go] = vh;
            g_hA_lo[go] = __float2bfloat16(v - __bfloat162float(vh));
        }
    }
}

// ===================== launch =====================
extern "C" void kernel_launch(void* const* d_in, const int* in_sizes, int n_in,
                              void* d_out, int out_size) {
    const int*   tok  = (const int*)  d_in[0];
    const float* mask = (const float*)d_in[1];
    const float* keys = (const float*)d_in[2];
    const float* emb  = (const float*)d_in[3];
    const float* U    = (const float*)d_in[4];
    const float* V    = (const float*)d_in[5];
    const float* W    = (const float*)d_in[6];
    float* h = (float*)d_out;

    cudaFuncSetAttribute(step_kernel, cudaFuncAttributeMaxDynamicSharedMemorySize, SMEM_BYTES);

    float *enc, *eW, *kV;
    void *hhi, *hlo;
    cudaGetSymbolAddress((void**)&enc, g_enc);
    cudaGetSymbolAddress((void**)&eW,  g_eW);
    cudaGetSymbolAddress((void**)&kV,  g_kV);
    cudaGetSymbolAddress(&hhi, g_hA_hi);
    cudaGetSymbolAddress(&hlo, g_hA_lo);

    encode_kernel<<<NB*NS, ND>>>(tok, mask, emb);
    gemm0_kernel<<<dim3(2, (NB*NE)/128), 256>>>(keys, V, kV);
    gemm0_kernel<<<dim3(2, (NB*NS)/128), 256>>>(enc,  W, eW);
    prep_bt_kernel<<<ND, ND>>>(U);

    cudaMemsetAsync(h,   0, (size_t)NB*NE*ND*sizeof(float), 0);
    cudaMemsetAsync(hhi, 0, (size_t)NB*NE*ND*sizeof(__nv_bfloat16), 0);
    cudaMemsetAsync(hlo, 0, (size_t)NB*NE*ND*sizeof(__nv_bfloat16), 0);

    for (int s = 0; s < NS; ++s) {
        step_kernel<<<128, 512, SMEM_BYTES>>>(keys, h, s);
    }
}

// round 4
// speedup vs baseline: 2.0485x; 1.1394x over previous
#include <cuda_runtime.h>
#include <cuda_bf16.h>
#include <cstdint>
#include <math.h>

#define NB 256
#define NS 32
#define NL 32
#define ND 256
#define NE 64
#define KBIG 768          // concatenated K: [hi | hi | lo] x [Uhi ; Ulo ; Uhi]

// ===================== scratch (device globals; no runtime alloc) =====================
__device__ float g_enc[NB*NS*ND];            // enc[b,s,d]
__device__ float g_eW [NB*NS*ND];            // enc @ W
__device__ float g_kV [NB*NE*ND];            // keys @ V
__device__ int   g_act[NB*NS];
__device__ float g_dotEK[NB*NS*NE];          // enc_s . keys_j  (invariant)
__device__ float g_gdot[NB*NE];              // enc_{s} . h_{s-1} (rolled forward)
__device__ __nv_bfloat16 g_Bt[ND*KBIG];      // Bt[n][k]: [Uhi^T | Ulo^T | Uhi^T]
__device__ __nv_bfloat16 g_hA_hi[NB*NE*ND];  // h split hi (row,k)
__device__ __nv_bfloat16 g_hA_lo[NB*NE*ND];  // h split lo

// ===================== PTX wrappers (sm_80-level features only) =====================
__device__ __forceinline__ uint32_t smem_u32(const void* p) {
    uint32_t a;
    asm("{ .reg .u64 t; cvta.to.shared.u64 t, %1; cvt.u32.u64 %0, t; }" : "=r"(a) : "l"(p));
    return a;
}
__device__ __forceinline__ void cpa16(uint32_t dst, const void* src) {
    asm volatile("cp.async.cg.shared.global [%0], [%1], 16;" :: "r"(dst), "l"(src));
}
#define CP_COMMIT() asm volatile("cp.async.commit_group;" ::: "memory")
#define CP_WAIT1()  asm volatile("cp.async.wait_group 1;"  ::: "memory")
#define CP_WAIT0()  asm volatile("cp.async.wait_group 0;"  ::: "memory")

__device__ __forceinline__ void ldsm_x4(uint32_t* r, uint32_t addr) {
    asm volatile("ldmatrix.sync.aligned.m8n8.x4.shared.b16 {%0,%1,%2,%3}, [%4];"
        : "=r"(r[0]), "=r"(r[1]), "=r"(r[2]), "=r"(r[3]) : "r"(addr));
}
__device__ __forceinline__ void ldsm_x2(uint32_t* r, uint32_t addr) {
    asm volatile("ldmatrix.sync.aligned.m8n8.x2.shared.b16 {%0,%1}, [%2];"
        : "=r"(r[0]), "=r"(r[1]) : "r"(addr));
}
__device__ __forceinline__ void mma_bf16(float* d, const uint32_t* a, const uint32_t* b) {
    asm volatile("mma.sync.aligned.m16n8k16.row.col.f32.bf16.bf16.f32 "
        "{%0,%1,%2,%3}, {%4,%5,%6,%7}, {%8,%9}, {%0,%1,%2,%3};"
        : "+f"(d[0]), "+f"(d[1]), "+f"(d[2]), "+f"(d[3])
        : "r"(a[0]), "r"(a[1]), "r"(a[2]), "r"(a[3]), "r"(b[0]), "r"(b[1]));
}

// ===================== SMEM layout for step kernel =====================
// tile rows padded to 72 bf16 = 144B -> conflict-free ldmatrix
#define SM_GATE 0
#define SM_RSQ  512
#define SM_DV   1024
#define SM_DH   1536
#define SM_ACTS 2048
#define SM_ST0  4096
#define A_TILE_B (128*144)             // 18432
#define B_TILE_B (256*144)             // 36864
#define STAGE_B  (A_TILE_B + B_TILE_B) // 55296
#define SMEM_BYTES (SM_ST0 + 3*STAGE_B)    // 169984

// ===================== encode =====================
__global__ void encode_kernel(const int* __restrict__ tok, const float* __restrict__ mask,
                              const float* __restrict__ emb) {
    int bs = blockIdx.x, d = threadIdx.x;
    const int*   t = tok  + (size_t)bs*NL;
    const float* m = mask + (size_t)bs*NL;
    float acc = 0.f, ms = 0.f;
    #pragma unroll
    for (int l = 0; l < NL; ++l) {
        float mv = __ldg(m + l);
        int   tv = __ldg(t + l);
        acc += mv * __ldg(emb + (size_t)tv*ND + d);
        ms  += mv;
    }
    g_enc[(size_t)bs*ND + d] = acc;
    if (d == 0) g_act[bs] = (ms > 0.f) ? 1 : 0;
}

// ===================== prep: Bt[n][k] = [Uhi^T | Ulo^T | Uhi^T] =====================
__global__ void prep_bt_kernel(const float* __restrict__ U) {
    int n = blockIdx.x, k = threadIdx.x;
    float v = U[(size_t)k*ND + n];
    __nv_bfloat16 hi = __float2bfloat16(v);
    __nv_bfloat16 lo = __float2bfloat16(v - __bfloat162float(hi));
    g_Bt[(size_t)n*KBIG + k]        = hi;
    g_Bt[(size_t)n*KBIG + 256 + k]  = lo;
    g_Bt[(size_t)n*KBIG + 512 + k]  = hi;
}

// ===================== dotEK: enc_s . keys_j per (b,s,j) (invariant) ================
// one block per b; keys[b] cached in swizzled smem (64KB) + enc row (1KB)
__global__ void dotek_kernel(const float* __restrict__ keys) {
    extern __shared__ float dsm[];          // sk[16384] + se[256]
    float* sk = dsm;
    float* se = dsm + NE*ND;
    const int b = blockIdx.x, tid = threadIdx.x;
    const int j = tid >> 2, part = tid & 3;
    const int sw = (j & 7) << 2;            // xor swizzle (float4-safe)

    // load keys[b] swizzled
    #pragma unroll
    for (int i = 0; i < 16; i++) {
        int d0 = part*64 + i*4;
        float4 v = *(const float4*)(keys + ((size_t)b*NE + j)*ND + d0);
        *(float4*)&sk[(j << 8) + (d0 ^ sw)] = v;
    }
    __syncthreads();

    for (int s = 0; s < NS; ++s) {
        se[tid] = g_enc[((size_t)b*NS + s)*ND + tid];
        __syncthreads();
        float p = 0.f;
        #pragma unroll
        for (int i = 0; i < 16; i++) {
            int d0 = part*64 + i*4;
            float4 kv = *(const float4*)&sk[(j << 8) + (d0 ^ sw)];
            p += kv.x*se[d0] + kv.y*se[d0+1] + kv.z*se[d0+2] + kv.w*se[d0+3];
        }
        p += __shfl_xor_sync(0xffffffffu, p, 1);
        p += __shfl_xor_sync(0xffffffffu, p, 2);
        if (part == 0) g_dotEK[((size_t)b*NS + s)*NE + j] = p;
        __syncthreads();
    }
}

// ===================== merged SIMT fp32 GEMM: kV = keys@V, eW = enc@W ================
__global__ __launch_bounds__(256, 2)
void gemm0_merged(const float* __restrict__ keys, const float* __restrict__ V,
                  const float* __restrict__ W) {
    const int BK = 8;
    __shared__ float As[BK][128];
    __shared__ float Bs[BK][128];
    const int tid = threadIdx.x;
    const int trow = tid >> 4, tcol = tid & 15;
    const float *A, *Bm; float* C; int rowBase;
    if (blockIdx.y < 128) { A = keys;  Bm = V; C = g_kV; rowBase = blockIdx.y * 128; }
    else                  { A = g_enc; Bm = W; C = g_eW; rowBase = (blockIdx.y - 128) * 128; }
    const int colBase = blockIdx.x * 128;
    const int aRow = tid >> 1, aK4 = (tid & 1) * 4;
    const int bK = tid >> 5, bCol = (tid & 31) * 4;
    float acc[8][8];
    #pragma unroll
    for (int i = 0; i < 8; i++)
        #pragma unroll
        for (int j = 0; j < 8; j++) acc[i][j] = 0.f;
    const float* Ag = A  + (size_t)(rowBase + aRow)*ND + aK4;
    const float* Bg = Bm + (size_t)bK*ND + colBase + bCol;
    for (int k0 = 0; k0 < ND; k0 += BK) {
        float4 av = *(const float4*)(Ag + k0);
        As[aK4+0][aRow] = av.x; As[aK4+1][aRow] = av.y;
        As[aK4+2][aRow] = av.z; As[aK4+3][aRow] = av.w;
        *(float4*)(&Bs[bK][bCol]) = *(const float4*)(Bg + (size_t)k0*ND);
        __syncthreads();
        #pragma unroll
        for (int k = 0; k < BK; k++) {
            float rm[8], rn[8];
            *(float4*)(rm)     = *(const float4*)(&As[k][trow*8]);
            *(float4*)(rm + 4) = *(const float4*)(&As[k][trow*8 + 4]);
            *(float4*)(rn)     = *(const float4*)(&Bs[k][tcol*8]);
            *(float4*)(rn + 4) = *(const float4*)(&Bs[k][tcol*8 + 4]);
            #pragma unroll
            for (int i = 0; i < 8; i++)
                #pragma unroll
                for (int j = 0; j < 8; j++)
                    acc[i][j] = fmaf(rm[i], rn[j], acc[i][j]);
        }
        __syncthreads();
    }
    #pragma unroll
    for (int i = 0; i < 8; i++) {
        size_t off = (size_t)(rowBase + trow*8 + i)*ND + colBase + tcol*8;
        *(float4*)(C + off)     = make_float4(acc[i][0], acc[i][1], acc[i][2], acc[i][3]);
        *(float4*)(C + off + 4) = make_float4(acc[i][4], acc[i][5], acc[i][6], acc[i][7]);
    }
}

// ===================== fused step: HMMA GEMM + gate + norm + next-gate dot ===========
__global__ void __launch_bounds__(512, 1)
step_kernel(const float* __restrict__ keys, float* __restrict__ h, int s) {
    extern __shared__ char smem[];
    const uint32_t sb = smem_u32(smem);
    const int tid    = threadIdx.x;
    const int lane   = tid & 31;
    const int wid    = tid >> 5;
    const int warp_m = wid >> 2;          // 0..3 -> 32 rows each
    const int warp_n = wid & 3;           // 0..3 -> 64 cols each
    const int rowBase = blockIdx.x * 128;

    float* gs   = (float*)(smem + SM_GATE);
    float* rs   = (float*)(smem + SM_RSQ);
    float* dV   = (float*)(smem + SM_DV);
    float* dH   = (float*)(smem + SM_DH);
    int*   acts = (int*)  (smem + SM_ACTS);

    // ---------- init: gate from precomputed dots ----------
    if (tid < 128) {
        int grow = rowBase + tid;
        int b = grow >> 6, j = grow & 63;
        float gd = g_gdot[grow] + g_dotEK[((size_t)b*NS + s)*NE + j];
        gs[tid]   = 1.f / (1.f + expf(-gd));
        acts[tid] = g_act[b*NS + s];
        rs[tid] = 0.f; dV[tid] = 0.f; dH[tid] = 0.f;
    }

    // ---------- mainloop: C[128,256] += Abig[128,768] @ Bt^T, 12 chunks K=64 ---------
    const __nv_bfloat16* hi = g_hA_hi + (size_t)rowBase*ND;
    const __nv_bfloat16* lo = g_hA_lo + (size_t)rowBase*ND;

    float acc[2][8][4];
    #pragma unroll
    for (int mt = 0; mt < 2; mt++)
        #pragma unroll
        for (int nt = 0; nt < 8; nt++)
            #pragma unroll
            for (int q = 0; q < 4; q++) acc[mt][nt][q] = 0.f;

    const int selA = lane >> 3;
    const uint32_t aoff = (uint32_t)(((selA & 1)*8 + (lane & 7))*144 + (selA >> 1)*16);
    const int l16 = lane & 15;
    const uint32_t boff = (uint32_t)((l16 & 7)*144 + (l16 >> 3)*16);

    auto load_chunk = [&](int c, int slot) {
        const __nv_bfloat16* asrc = ((c < 8) ? hi : lo) + (c & 3)*64;
        const __nv_bfloat16* bsrc = g_Bt + c*64;
        uint32_t adst = sb + SM_ST0 + (uint32_t)slot*STAGE_B;
        uint32_t bdst = adst + A_TILE_B;
        #pragma unroll
        for (int i = 0; i < 2; i++) {
            int idx = tid + i*512, row = idx >> 3, seg = idx & 7;
            cpa16(adst + row*144 + seg*16, asrc + (size_t)row*ND + seg*8);
        }
        #pragma unroll
        for (int i = 0; i < 4; i++) {
            int idx = tid + i*512, n = idx >> 3, seg = idx & 7;
            cpa16(bdst + n*144 + seg*16, bsrc + (size_t)n*KBIG + seg*8);
        }
    };

    load_chunk(0, 0); CP_COMMIT();
    load_chunk(1, 1); CP_COMMIT();

    #pragma unroll
    for (int c = 0; c < 12; ++c) {
        if (c < 11) CP_WAIT1(); else CP_WAIT0();
        __syncthreads();                       // data visible; prior compute done
        if (c < 10) { load_chunk(c + 2, (c + 2) % 3); CP_COMMIT(); }

        const uint32_t abase = sb + SM_ST0 + (uint32_t)(c % 3)*STAGE_B + (warp_m*32)*144 + aoff;
        const uint32_t bbase = sb + SM_ST0 + (uint32_t)(c % 3)*STAGE_B + A_TILE_B + (warp_n*64)*144 + boff;

        #pragma unroll
        for (int k4 = 0; k4 < 4; ++k4) {
            const uint32_t kb = k4 * 32;
            uint32_t a0[4], a1[4];
            ldsm_x4(a0, abase + kb);
            ldsm_x4(a1, abase + 16*144 + kb);
            #pragma unroll
            for (int nt = 0; nt < 8; ++nt) {
                uint32_t bfrag[2];
                ldsm_x2(bfrag, bbase + nt*8*144 + kb);
                mma_bf16(acc[0][nt], a0, bfrag);
                mma_bf16(acc[1][nt], a1, bfrag);
            }
        }
    }

    // ---------- epilogue pass 1: relu-add, gated update, sumsq + next-step dots ------
    const int sn = (s + 1 < NS) ? s + 1 : NS - 1;
    #pragma unroll
    for (int mt = 0; mt < 2; mt++) {
        int rA = warp_m*32 + mt*16 + (lane >> 2);
        int rB = rA + 8;
        int gA = rowBase + rA, gB = rowBase + rB;
        int bA = gA >> 6;
        const float* kvA = g_kV + (size_t)gA*ND;
        const float* kvB = g_kV + (size_t)gB*ND;
        const float* ewR = g_eW  + ((size_t)bA*NS + s )*ND;   // same b for rA,rB
        const float* enN = g_enc + ((size_t)bA*NS + sn)*ND;
        const float* hA  = h    + (size_t)gA*ND;
        const float* hB  = h    + (size_t)gB*ND;
        float gateA = gs[rA], gateB = gs[rB];
        float sA = 0.f, sB = 0.f;
        float dVA = 0.f, dVB = 0.f, dHA = 0.f, dHB = 0.f;
        #pragma unroll
        for (int nt = 0; nt < 8; nt++) {
            int col = warp_n*64 + nt*8 + 2*(lane & 3);
            float2 en = *(const float2*)(enN + col);
            float2 ew = *(const float2*)(ewR + col);
            float2 kv, ho;
            kv = *(const float2*)(kvA + col); ho = *(const float2*)(hA + col);
            float v0 = fmaxf(acc[mt][nt][0] + kv.x + ew.x, 0.f);
            float v1 = fmaxf(acc[mt][nt][1] + kv.y + ew.y, 0.f);
            float h0 = ho.x + gateA*v0, h1 = ho.y + gateA*v1;
            acc[mt][nt][0] = h0; acc[mt][nt][1] = h1;
            sA  += h0*h0 + h1*h1;
            dVA += en.x*h0 + en.y*h1;
            dHA += en.x*ho.x + en.y*ho.y;
            kv = *(const float2*)(kvB + col); ho = *(const float2*)(hB + col);
            float w0 = fmaxf(acc[mt][nt][2] + kv.x + ew.x, 0.f);
            float w1 = fmaxf(acc[mt][nt][3] + kv.y + ew.y, 0.f);
            float h2 = ho.x + gateB*w0, h3 = ho.y + gateB*w1;
            acc[mt][nt][2] = h2; acc[mt][nt][3] = h3;
            sB  += h2*h2 + h3*h3;
            dVB += en.x*h2 + en.y*h3;
            dHB += en.x*ho.x + en.y*ho.y;
        }
        #pragma unroll
        for (int o = 1; o <= 2; o <<= 1) {
            sA  += __shfl_xor_sync(0xffffffffu, sA,  o);
            sB  += __shfl_xor_sync(0xffffffffu, sB,  o);
            dVA += __shfl_xor_sync(0xffffffffu, dVA, o);
            dVB += __shfl_xor_sync(0xffffffffu, dVB, o);
            dHA += __shfl_xor_sync(0xffffffffu, dHA, o);
            dHB += __shfl_xor_sync(0xffffffffu, dHB, o);
        }
        if ((lane & 3) == 0) {
            atomicAdd(&rs[rA], sA);  atomicAdd(&rs[rB], sB);
            atomicAdd(&dV[rA], dVA); atomicAdd(&dV[rB], dVB);
            atomicAdd(&dH[rA], dHA); atomicAdd(&dH[rB], dHB);
        }
    }
    __syncthreads();
    if (tid < 128) {
        float r = rsqrtf(fmaxf(rs[tid], 1e-12f));
        rs[tid] = r;
        g_gdot[rowBase + tid] = acts[tid] ? dV[tid]*r : dH[tid];
    }
    __syncthreads();

    // ---------- epilogue pass 2: in-register normalize + write h / bf16 hi/lo --------
    #pragma unroll
    for (int mt = 0; mt < 2; mt++) {
        int rA = warp_m*32 + mt*16 + (lane >> 2);
        int rB = rA + 8;
        float rnA = rs[rA], rnB = rs[rB];
        int aA = acts[rA], aB = acts[rB];
        size_t gOA = (size_t)(rowBase + rA)*ND;
        size_t gOB = (size_t)(rowBase + rB)*ND;
        #pragma unroll
        for (int nt = 0; nt < 8; nt++) {
            int col = warp_n*64 + nt*8 + 2*(lane & 3);
            if (aA) {
                float v0 = acc[mt][nt][0]*rnA, v1 = acc[mt][nt][1]*rnA;
                *(float2*)(h + gOA + col) = make_float2(v0, v1);
                __nv_bfloat16 h0 = __float2bfloat16(v0), h1 = __float2bfloat16(v1);
                *(__nv_bfloat162*)(g_hA_hi + gOA + col) = __nv_bfloat162(h0, h1);
                *(__nv_bfloat162*)(g_hA_lo + gOA + col) = __nv_bfloat162(
                    __float2bfloat16(v0 - __bfloat162float(h0)),
                    __float2bfloat16(v1 - __bfloat162float(h1)));
            }
            if (aB) {
                float v0 = acc[mt][nt][2]*rnB, v1 = acc[mt][nt][3]*rnB;
                *(float2*)(h + gOB + col) = make_float2(v0, v1);
                __nv_bfloat16 h0 = __float2bfloat16(v0), h1 = __float2bfloat16(v1);
                *(__nv_bfloat162*)(g_hA_hi + gOB + col) = __nv_bfloat162(h0, h1);
                *(__nv_bfloat162*)(g_hA_lo + gOB + col) = __nv_bfloat162(
                    __float2bfloat16(v0 - __bfloat162float(h0)),
                    __float2bfloat16(v1 - __bfloat162float(h1)));
            }
        }
    }
}

// ===================== launch =====================
extern "C" void kernel_launch(void* const* d_in, const int* in_sizes, int n_in,
                              void* d_out, int out_size) {
    const int*   tok  = (const int*)  d_in[0];
    const float* mask = (const float*)d_in[1];
    const float* keys = (const float*)d_in[2];
    const float* emb  = (const float*)d_in[3];
    const float* U    = (const float*)d_in[4];
    const float* V    = (const float*)d_in[5];
    const float* W    = (const float*)d_in[6];
    float* h = (float*)d_out;

    cudaFuncSetAttribute(step_kernel,  cudaFuncAttributeMaxDynamicSharedMemorySize, SMEM_BYTES);
    cudaFuncSetAttribute(dotek_kernel, cudaFuncAttributeMaxDynamicSharedMemorySize, (NE*ND + ND)*4);

    void *hhi, *hlo, *gdot;
    cudaGetSymbolAddress(&hhi,  g_hA_hi);
    cudaGetSymbolAddress(&hlo,  g_hA_lo);
    cudaGetSymbolAddress(&gdot, g_gdot);

    encode_kernel<<<NB*NS, ND>>>(tok, mask, emb);
    gemm0_merged<<<dim3(2, 192), 256>>>(keys, V, W);
    prep_bt_kernel<<<ND, ND>>>(U);
    dotek_kernel<<<NB, 256, (NE*ND + ND)*4>>>(keys);

    cudaMemsetAsync(h,    0, (size_t)NB*NE*ND*sizeof(float), 0);
    cudaMemsetAsync(hhi,  0, (size_t)NB*NE*ND*sizeof(__nv_bfloat16), 0);
    cudaMemsetAsync(hlo,  0, (size_t)NB*NE*ND*sizeof(__nv_bfloat16), 0);
    cudaMemsetAsync(gdot, 0, (size_t)NB*NE*sizeof(float), 0);

    for (int s = 0; s < NS; ++s) {
        step_kernel<<<128, 512, SMEM_BYTES>>>(keys, h, s);
    }
}

// round 5
// speedup vs baseline: 2.1248x; 1.0372x over previous
#include <cuda_runtime.h>
#include <cuda_bf16.h>
#include <cstdint>
#include <math.h>

#define NB 256
#define NS 32
#define NL 32
#define ND 256
#define NE 64
#define KBIG 768          // concatenated K: [hi | hi | lo] x [Uhi ; Ulo ; Uhi]

// ===================== scratch (device globals; no runtime alloc) =====================
__device__ float g_enc[NB*NS*ND];            // enc[b,s,d]
__device__ float g_eW [NB*NS*ND];            // enc @ W
__device__ float g_kV [NB*NE*ND];            // keys @ V
__device__ int   g_act[NB*NS];
__device__ float g_dotEK[NB*NS*NE];          // enc_s . keys_j  (invariant)
__device__ __nv_bfloat16 g_Bt[ND*KBIG];      // Bt[n][k]: [Uhi^T | Ulo^T | Uhi^T]
__device__ __nv_bfloat16 g_hA_hi[NB*NE*ND];  // h split hi (row,k)
__device__ __nv_bfloat16 g_hA_lo[NB*NE*ND];  // h split lo

// ===================== PTX wrappers (sm_80-level features only) =====================
__device__ __forceinline__ uint32_t smem_u32(const void* p) {
    uint32_t a;
    asm("{ .reg .u64 t; cvta.to.shared.u64 t, %1; cvt.u32.u64 %0, t; }" : "=r"(a) : "l"(p));
    return a;
}
__device__ __forceinline__ void cpa16(uint32_t dst, const void* src) {
    asm volatile("cp.async.cg.shared.global [%0], [%1], 16;" :: "r"(dst), "l"(src));
}
#define CP_COMMIT() asm volatile("cp.async.commit_group;" ::: "memory")
#define CP_WAIT1()  asm volatile("cp.async.wait_group 1;"  ::: "memory")
#define CP_WAIT0()  asm volatile("cp.async.wait_group 0;"  ::: "memory")

__device__ __forceinline__ void ldsm_x4(uint32_t* r, uint32_t addr) {
    asm volatile("ldmatrix.sync.aligned.m8n8.x4.shared.b16 {%0,%1,%2,%3}, [%4];"
        : "=r"(r[0]), "=r"(r[1]), "=r"(r[2]), "=r"(r[3]) : "r"(addr));
}
__device__ __forceinline__ void ldsm_x2(uint32_t* r, uint32_t addr) {
    asm volatile("ldmatrix.sync.aligned.m8n8.x2.shared.b16 {%0,%1}, [%2];"
        : "=r"(r[0]), "=r"(r[1]) : "r"(addr));
}
__device__ __forceinline__ void mma_bf16(float* d, const uint32_t* a, const uint32_t* b) {
    asm volatile("mma.sync.aligned.m16n8k16.row.col.f32.bf16.bf16.f32 "
        "{%0,%1,%2,%3}, {%4,%5,%6,%7}, {%8,%9}, {%0,%1,%2,%3};"
        : "+f"(d[0]), "+f"(d[1]), "+f"(d[2]), "+f"(d[3])
        : "r"(a[0]), "r"(a[1]), "r"(a[2]), "r"(a[3]), "r"(b[0]), "r"(b[1]));
}

// ===================== SMEM layout for persistent step kernel =====================
#define SM_GATE 0
#define SM_RSQ  512
#define SM_DV   1024
#define SM_DH   1536
#define SM_GN   2048
#define SM_ACTS 2560
#define SM_ST0  4096
#define A_TILE_B (128*144)             // 18432 (rows padded to 144B)
#define B_TILE_B (256*144)             // 36864
#define STAGE_B  (A_TILE_B + B_TILE_B) // 55296
#define SMEM_BYTES (SM_ST0 + 3*STAGE_B)    // 169984

// ===================== encode =====================
__global__ void encode_kernel(const int* __restrict__ tok, const float* __restrict__ mask,
                              const float* __restrict__ emb) {
    int bs = blockIdx.x, d = threadIdx.x;
    const int*   t = tok  + (size_t)bs*NL;
    const float* m = mask + (size_t)bs*NL;
    float acc = 0.f, ms = 0.f;
    #pragma unroll
    for (int l = 0; l < NL; ++l) {
        float mv = __ldg(m + l);
        int   tv = __ldg(t + l);
        acc += mv * __ldg(emb + (size_t)tv*ND + d);
        ms  += mv;
    }
    g_enc[(size_t)bs*ND + d] = acc;
    if (d == 0) g_act[bs] = (ms > 0.f) ? 1 : 0;
}

// ===================== prep: Bt[n][k] = [Uhi^T | Ulo^T | Uhi^T] =====================
__global__ void prep_bt_kernel(const float* __restrict__ U) {
    int n = blockIdx.x, k = threadIdx.x;
    float v = U[(size_t)k*ND + n];
    __nv_bfloat16 hi = __float2bfloat16(v);
    __nv_bfloat16 lo = __float2bfloat16(v - __bfloat162float(hi));
    g_Bt[(size_t)n*KBIG + k]        = hi;
    g_Bt[(size_t)n*KBIG + 256 + k]  = lo;
    g_Bt[(size_t)n*KBIG + 512 + k]  = hi;
}

// ===================== dotEK: enc_s . keys_j (invariant), fast version ===============
// one CTA per b; enc[b] (32KB) in smem; each thread keeps 2 key-rows x 32 d in regs
__global__ __launch_bounds__(256)
void dotek_kernel(const float* __restrict__ keys) {
    __shared__ float se[NS*ND];                 // 32 KB
    const int b = blockIdx.x, tid = threadIdx.x;
    const float4* esrc = (const float4*)(g_enc + (size_t)b*NS*ND);
    #pragma unroll
    for (int i = 0; i < 8; i++)
        ((float4*)se)[tid + i*256] = esrc[tid + i*256];
    __syncthreads();

    const int j = tid >> 3, part = tid & 7;     // j 0..31, part 0..7 (32 d each)
    float4 k0[8], k1[8];
    const float4* kr0 = (const float4*)(keys + ((size_t)b*NE + j     )*ND + part*32);
    const float4* kr1 = (const float4*)(keys + ((size_t)b*NE + j + 32)*ND + part*32);
    #pragma unroll
    for (int i = 0; i < 8; i++) { k0[i] = kr0[i]; k1[i] = kr1[i]; }

    for (int s = 0; s < NS; ++s) {
        const float4* es = (const float4*)(se + s*ND + part*32);
        float d0 = 0.f, d1 = 0.f;
        #pragma unroll
        for (int i = 0; i < 8; i++) {
            float4 e = es[i];
            d0 += k0[i].x*e.x + k0[i].y*e.y + k0[i].z*e.z + k0[i].w*e.w;
            d1 += k1[i].x*e.x + k1[i].y*e.y + k1[i].z*e.z + k1[i].w*e.w;
        }
        #pragma unroll
        for (int o = 1; o <= 4; o <<= 1) {
            d0 += __shfl_xor_sync(0xffffffffu, d0, o);
            d1 += __shfl_xor_sync(0xffffffffu, d1, o);
        }
        if (part == 0) {
            g_dotEK[((size_t)b*NS + s)*NE + j]      = d0;
            g_dotEK[((size_t)b*NS + s)*NE + j + 32] = d1;
        }
    }
}

// ===================== merged SIMT fp32 GEMM: kV = keys@V, eW = enc@W ================
__global__ __launch_bounds__(256, 2)
void gemm0_merged(const float* __restrict__ keys, const float* __restrict__ V,
                  const float* __restrict__ W) {
    const int BK = 8;
    __shared__ float As[BK][128];
    __shared__ float Bs[BK][128];
    const int tid = threadIdx.x;
    const int trow = tid >> 4, tcol = tid & 15;
    const float *A, *Bm; float* C; int rowBase;
    if (blockIdx.y < 128) { A = keys;  Bm = V; C = g_kV; rowBase = blockIdx.y * 128; }
    else                  { A = g_enc; Bm = W; C = g_eW; rowBase = (blockIdx.y - 128) * 128; }
    const int colBase = blockIdx.x * 128;
    const int aRow = tid >> 1, aK4 = (tid & 1) * 4;
    const int bK = tid >> 5, bCol = (tid & 31) * 4;
    float acc[8][8];
    #pragma unroll
    for (int i = 0; i < 8; i++)
        #pragma unroll
        for (int j = 0; j < 8; j++) acc[i][j] = 0.f;
    const float* Ag = A  + (size_t)(rowBase + aRow)*ND + aK4;
    const float* Bg = Bm + (size_t)bK*ND + colBase + bCol;
    for (int k0 = 0; k0 < ND; k0 += BK) {
        float4 av = *(const float4*)(Ag + k0);
        As[aK4+0][aRow] = av.x; As[aK4+1][aRow] = av.y;
        As[aK4+2][aRow] = av.z; As[aK4+3][aRow] = av.w;
        *(float4*)(&Bs[bK][bCol]) = *(const float4*)(Bg + (size_t)k0*ND);
        __syncthreads();
        #pragma unroll
        for (int k = 0; k < BK; k++) {
            float rm[8], rn[8];
            *(float4*)(rm)     = *(const float4*)(&As[k][trow*8]);
            *(float4*)(rm + 4) = *(const float4*)(&As[k][trow*8 + 4]);
            *(float4*)(rn)     = *(const float4*)(&Bs[k][tcol*8]);
            *(float4*)(rn + 4) = *(const float4*)(&Bs[k][tcol*8 + 4]);
            #pragma unroll
            for (int i = 0; i < 8; i++)
                #pragma unroll
                for (int j = 0; j < 8; j++)
                    acc[i][j] = fmaf(rm[i], rn[j], acc[i][j]);
        }
        __syncthreads();
    }
    #pragma unroll
    for (int i = 0; i < 8; i++) {
        size_t off = (size_t)(rowBase + trow*8 + i)*ND + colBase + tcol*8;
        *(float4*)(C + off)     = make_float4(acc[i][0], acc[i][1], acc[i][2], acc[i][3]);
        *(float4*)(C + off + 4) = make_float4(acc[i][4], acc[i][5], acc[i][6], acc[i][7]);
    }
}

// ===================== persistent fused recurrence: all 32 steps in one launch =======
__global__ void __launch_bounds__(512, 1)
steps_kernel(float* __restrict__ h) {
    extern __shared__ char smem[];
    const uint32_t sb = smem_u32(smem);
    const int tid    = threadIdx.x;
    const int lane   = tid & 31;
    const int wid    = tid >> 5;
    const int warp_m = wid >> 2;          // 0..3 -> 32 rows each
    const int warp_n = wid & 3;           // 0..3 -> 64 cols each
    const int rowBase = blockIdx.x * 128;

    float* gs   = (float*)(smem + SM_GATE);
    float* rs   = (float*)(smem + SM_RSQ);
    float* dV   = (float*)(smem + SM_DV);
    float* dH   = (float*)(smem + SM_DH);
    float* gn   = (float*)(smem + SM_GN);
    int*   acts = (int*)  (smem + SM_ACTS);

    if (tid < 128) gn[tid] = 0.f;

    const __nv_bfloat16* hi = g_hA_hi + (size_t)rowBase*ND;
    const __nv_bfloat16* lo = g_hA_lo + (size_t)rowBase*ND;

    const int selA = lane >> 3;
    const uint32_t aoff = (uint32_t)(((selA & 1)*8 + (lane & 7))*144 + (selA >> 1)*16);
    const int l16 = lane & 15;
    const uint32_t boff = (uint32_t)((l16 & 7)*144 + (l16 >> 3)*16);

    auto load_chunk = [&](int c, int slot) {
        const __nv_bfloat16* asrc = ((c < 8) ? hi : lo) + (c & 3)*64;
        const __nv_bfloat16* bsrc = g_Bt + c*64;
        uint32_t adst = sb + SM_ST0 + (uint32_t)slot*STAGE_B;
        uint32_t bdst = adst + A_TILE_B;
        #pragma unroll
        for (int i = 0; i < 2; i++) {
            int idx = tid + i*512, row = idx >> 3, seg = idx & 7;
            cpa16(adst + row*144 + seg*16, asrc + (size_t)row*ND + seg*8);
        }
        #pragma unroll
        for (int i = 0; i < 4; i++) {
            int idx = tid + i*512, n = idx >> 3, seg = idx & 7;
            cpa16(bdst + n*144 + seg*16, bsrc + (size_t)n*KBIG + seg*8);
        }
    };

    for (int s = 0; s < NS; ++s) {
        const bool first = (s == 0);
        __syncthreads();                  // prev pass2 done; smem arrays reusable
        if (tid < 128) {
            int grow = rowBase + tid;
            int b = grow >> 6, j = grow & 63;
            gs[tid]   = 1.f / (1.f + expf(-(gn[tid] + g_dotEK[((size_t)b*NS + s)*NE + j])));
            acts[tid] = g_act[b*NS + s];
            rs[tid] = 0.f; dV[tid] = 0.f; dH[tid] = 0.f;
        }

        float acc[2][8][4];
        #pragma unroll
        for (int mt = 0; mt < 2; mt++)
            #pragma unroll
            for (int nt = 0; nt < 8; nt++)
                #pragma unroll
                for (int q = 0; q < 4; q++) acc[mt][nt][q] = 0.f;

        if (!first) {
            load_chunk(0, 0); CP_COMMIT();
            load_chunk(1, 1); CP_COMMIT();
            #pragma unroll
            for (int c = 0; c < 12; ++c) {
                if (c < 11) CP_WAIT1(); else CP_WAIT0();
                __syncthreads();
                if (c < 10) { load_chunk(c + 2, (c + 2) % 3); CP_COMMIT(); }
                const uint32_t base = sb + SM_ST0 + (uint32_t)(c % 3)*STAGE_B;
                const uint32_t abase = base + (warp_m*32)*144 + aoff;
                const uint32_t bbase = base + A_TILE_B + (warp_n*64)*144 + boff;
                #pragma unroll
                for (int k4 = 0; k4 < 4; ++k4) {
                    const uint32_t kb = k4 * 32;
                    uint32_t a0[4], a1[4];
                    ldsm_x4(a0, abase + kb);
                    ldsm_x4(a1, abase + 16*144 + kb);
                    #pragma unroll
                    for (int nt = 0; nt < 8; ++nt) {
                        uint32_t bfrag[2];
                        ldsm_x2(bfrag, bbase + nt*8*144 + kb);
                        mma_bf16(acc[0][nt], a0, bfrag);
                        mma_bf16(acc[1][nt], a1, bfrag);
                    }
                }
            }
        } else {
            __syncthreads();              // gs/acts visible for epilogue
        }

        // ---------- epilogue pass 1 ----------
        const int sn = (s + 1 < NS) ? s + 1 : NS - 1;
        #pragma unroll
        for (int mt = 0; mt < 2; mt++) {
            int rA = warp_m*32 + mt*16 + (lane >> 2);
            int rB = rA + 8;
            int gA = rowBase + rA, gB = rowBase + rB;
            int bA = gA >> 6;                         // rA,rB same b (16-aligned blocks)
            const float* kvA = g_kV + (size_t)gA*ND;
            const float* kvB = g_kV + (size_t)gB*ND;
            const float* ewR = g_eW  + ((size_t)bA*NS + s )*ND;
            const float* enN = g_enc + ((size_t)bA*NS + sn)*ND;
            const float* hA  = h    + (size_t)gA*ND;
            const float* hB  = h    + (size_t)gB*ND;
            float gateA = gs[rA], gateB = gs[rB];
            float sA = 0.f, sB = 0.f;
            float dVA = 0.f, dVB = 0.f, dHA = 0.f, dHB = 0.f;
            #pragma unroll
            for (int nt = 0; nt < 8; nt++) {
                int col = warp_n*64 + nt*8 + 2*(lane & 3);
                float2 en = *(const float2*)(enN + col);
                float2 ew = *(const float2*)(ewR + col);
                float2 kv, ho;
                kv = *(const float2*)(kvA + col);
                ho = first ? make_float2(0.f, 0.f) : *(const float2*)(hA + col);
                float v0 = fmaxf(acc[mt][nt][0] + kv.x + ew.x, 0.f);
                float v1 = fmaxf(acc[mt][nt][1] + kv.y + ew.y, 0.f);
                float h0 = ho.x + gateA*v0, h1 = ho.y + gateA*v1;
                acc[mt][nt][0] = h0; acc[mt][nt][1] = h1;
                sA  += h0*h0 + h1*h1;
                dVA += en.x*h0 + en.y*h1;
                dHA += en.x*ho.x + en.y*ho.y;
                kv = *(const float2*)(kvB + col);
                ho = first ? make_float2(0.f, 0.f) : *(const float2*)(hB + col);
                float w0 = fmaxf(acc[mt][nt][2] + kv.x + ew.x, 0.f);
                float w1 = fmaxf(acc[mt][nt][3] + kv.y + ew.y, 0.f);
                float h2 = ho.x + gateB*w0, h3 = ho.y + gateB*w1;
                acc[mt][nt][2] = h2; acc[mt][nt][3] = h3;
                sB  += h2*h2 + h3*h3;
                dVB += en.x*h2 + en.y*h3;
                dHB += en.x*ho.x + en.y*ho.y;
            }
            #pragma unroll
            for (int o = 1; o <= 2; o <<= 1) {
                sA  += __shfl_xor_sync(0xffffffffu, sA,  o);
                sB  += __shfl_xor_sync(0xffffffffu, sB,  o);
                dVA += __shfl_xor_sync(0xffffffffu, dVA, o);
                dVB += __shfl_xor_sync(0xffffffffu, dVB, o);
                dHA += __shfl_xor_sync(0xffffffffu, dHA, o);
                dHB += __shfl_xor_sync(0xffffffffu, dHB, o);
            }
            if ((lane & 3) == 0) {
                atomicAdd(&rs[rA], sA);  atomicAdd(&rs[rB], sB);
                atomicAdd(&dV[rA], dVA); atomicAdd(&dV[rB], dVB);
                atomicAdd(&dH[rA], dHA); atomicAdd(&dH[rB], dHB);
            }
        }
        __syncthreads();
        if (tid < 128) {
            float r = rsqrtf(fmaxf(rs[tid], 1e-12f));
            rs[tid] = r;
            gn[tid] = acts[tid] ? dV[tid]*r : dH[tid];
        }
        __syncthreads();

        // ---------- epilogue pass 2: normalize + write h / bf16 hi/lo ----------
        #pragma unroll
        for (int mt = 0; mt < 2; mt++) {
            int rA = warp_m*32 + mt*16 + (lane >> 2);
            int rB = rA + 8;
            float rnA = rs[rA], rnB = rs[rB];
            int aA = acts[rA], aB = acts[rB];
            size_t gOA = (size_t)(rowBase + rA)*ND;
            size_t gOB = (size_t)(rowBase + rB)*ND;
            #pragma unroll
            for (int nt = 0; nt < 8; nt++) {
                int col = warp_n*64 + nt*8 + 2*(lane & 3);
                if (aA || first) {
                    float v0 = aA ? acc[mt][nt][0]*rnA : 0.f;
                    float v1 = aA ? acc[mt][nt][1]*rnA : 0.f;
                    *(float2*)(h + gOA + col) = make_float2(v0, v1);
                    __nv_bfloat16 h0 = __float2bfloat16(v0), h1 = __float2bfloat16(v1);
                    *(__nv_bfloat162*)(g_hA_hi + gOA + col) = __nv_bfloat162(h0, h1);
                    *(__nv_bfloat162*)(g_hA_lo + gOA + col) = __nv_bfloat162(
                        __float2bfloat16(v0 - __bfloat162float(h0)),
                        __float2bfloat16(v1 - __bfloat162float(h1)));
                }
                if (aB || first) {
                    float v0 = aB ? acc[mt][nt][2]*rnB : 0.f;
                    float v1 = aB ? acc[mt][nt][3]*rnB : 0.f;
                    *(float2*)(h + gOB + col) = make_float2(v0, v1);
                    __nv_bfloat16 h0 = __float2bfloat16(v0), h1 = __float2bfloat16(v1);
                    *(__nv_bfloat162*)(g_hA_hi + gOB + col) = __nv_bfloat162(h0, h1);
                    *(__nv_bfloat162*)(g_hA_lo + gOB + col) = __nv_bfloat162(
                        __float2bfloat16(v0 - __bfloat162float(h0)),
                        __float2bfloat16(v1 - __bfloat162float(h1)));
                }
            }
        }
        __threadfence_block();            // h / g_hA writes visible to next step's loads
    }
}

// ===================== launch =====================
extern "C" void kernel_launch(void* const* d_in, const int* in_sizes, int n_in,
                              void* d_out, int out_size) {
    const int*   tok  = (const int*)  d_in[0];
    const float* mask = (const float*)d_in[1];
    const float* keys = (const float*)d_in[2];
    const float* emb  = (const float*)d_in[3];
    const float* U    = (const float*)d_in[4];
    const float* V    = (const float*)d_in[5];
    const float* W    = (const float*)d_in[6];
    float* h = (float*)d_out;

    cudaFuncSetAttribute(steps_kernel, cudaFuncAttributeMaxDynamicSharedMemorySize, SMEM_BYTES);

    encode_kernel<<<NB*NS, ND>>>(tok, mask, emb);
    gemm0_merged<<<dim3(2, 192), 256>>>(keys, V, W);
    prep_bt_kernel<<<ND, ND>>>(U);
    dotek_kernel<<<NB, 256>>>(keys);

    steps_kernel<<<128, 512, SMEM_BYTES>>>(h);
}